// round 10
// baseline (speedup 1.0000x reference)
#include <cuda_runtime.h>
#include <cuda_fp16.h>
#include <cstdint>
#include <math.h>

#define BB 16
#define LL 2048
#define DD 256
#define HH 8
#define HDIM 32
#define KWIN 7
#define NDEPTH 2
#define LOUT 1024
#define OCH 512
#define KCONV 768
#define NTOK (BB*LL)
#define Y_ELEMS (BB*LOUT*OCH)
#define LPAD (LL+2)

// ================= scratch =================
__device__ __half g_t0[(size_t)NTOK*DD];
__device__ __half g_qkvh[(size_t)NTOK*3*DD];
__device__ __half g_at[(size_t)NTOK*DD];
__device__ __half g_hi[(size_t)NTOK*4*DD];
__device__ __half g_xh2[(size_t)BB*LPAD*DD];
__device__ float  g_conv[(size_t)BB*LOUT*OCH];
__device__ __half g_wq[(size_t)NDEPTH*768*DD];
__device__ __half g_wp[(size_t)NDEPTH*DD*DD];
__device__ __half g_w1[(size_t)NDEPTH*1024*DD];
__device__ __half g_w2[(size_t)NDEPTH*DD*1024];
__device__ __half g_cw[(size_t)OCH*KCONV];

// ================= helpers =================
__device__ __forceinline__ uint32_t smem_u32(const void* p) {
    uint32_t a;
    asm("{ .reg .u64 t; cvta.to.shared.u64 t, %1; cvt.u32.u64 %0, t; }" : "=r"(a) : "l"(p));
    return a;
}
__device__ __forceinline__ void cp16(uint32_t s, const void* g) {
    asm volatile("cp.async.cg.shared.global [%0], [%1], 16;" :: "r"(s), "l"(g));
}
#define CP_COMMIT() asm volatile("cp.async.commit_group;" ::: "memory")
#define CP_WAIT(n)  asm volatile("cp.async.wait_group %0;" :: "n"(n) : "memory")

__device__ __forceinline__ void ldsm4(uint32_t* r, uint32_t addr) {
    asm volatile("ldmatrix.sync.aligned.m8n8.x4.shared.b16 {%0,%1,%2,%3}, [%4];"
        : "=r"(r[0]), "=r"(r[1]), "=r"(r[2]), "=r"(r[3]) : "r"(addr));
}
__device__ __forceinline__ void mma16816(float* c, const uint32_t* a, uint32_t b0, uint32_t b1) {
    asm volatile(
        "mma.sync.aligned.m16n8k16.row.col.f32.f16.f16.f32 "
        "{%0,%1,%2,%3}, {%4,%5,%6,%7}, {%8,%9}, {%0,%1,%2,%3};"
        : "+f"(c[0]), "+f"(c[1]), "+f"(c[2]), "+f"(c[3])
        : "r"(a[0]), "r"(a[1]), "r"(a[2]), "r"(a[3]), "r"(b0), "r"(b1));
}

__device__ __forceinline__ float blockReduceSum(float v) {
    __shared__ float s[8];
    int lane = threadIdx.x & 31, w = threadIdx.x >> 5;
    #pragma unroll
    for (int o = 16; o; o >>= 1) v += __shfl_xor_sync(0xffffffffu, v, o);
    if (lane == 0) s[w] = v;
    __syncthreads();
    if (w == 0) {
        v = (lane < 8) ? s[lane] : 0.0f;
        #pragma unroll
        for (int o = 4; o; o >>= 1) v += __shfl_xor_sync(0xffffffffu, v, o);
        if (lane == 0) s[0] = v;
    }
    __syncthreads();
    float r = s[0];
    __syncthreads();
    return r;
}

// ================= weight prep =================
#define S_WQ  (768*DD)
#define S_WP  (DD*DD)
#define S_W1  (1024*DD)
#define S_W2  (DD*1024)
#define LAYER_ELEMS (S_WQ + S_WP + S_W1 + S_W2)
#define PREP_TOTAL  (2*LAYER_ELEMS + OCH*KCONV)

__device__ __forceinline__ __half tr_h(const float* src, int j, int K, int N) {
    int n = j / K, kk = j % K;
    return __float2half_rn(src[(size_t)kk * N + n]);
}

__global__ void prep_kernel(const float* __restrict__ qkv_w, const float* __restrict__ proj_w,
                            const float* __restrict__ fc1_w, const float* __restrict__ fc2_w,
                            const float* __restrict__ conv_w,
                            __half* __restrict__ wq, __half* __restrict__ wp,
                            __half* __restrict__ w1, __half* __restrict__ w2,
                            __half* __restrict__ cw) {
    int i = blockIdx.x * blockDim.x + threadIdx.x;
    if (i >= PREP_TOTAL) return;
    if (i < 2 * LAYER_ELEMS) {
        int layer = i / LAYER_ELEMS;
        int j = i - layer * LAYER_ELEMS;
        if (j < S_WQ)
            wq[(size_t)layer * S_WQ + j] = tr_h(qkv_w + (size_t)layer * S_WQ, j, DD, 768);
        else if (j < S_WQ + S_WP)
            wp[(size_t)layer * S_WP + (j - S_WQ)] = tr_h(proj_w + (size_t)layer * S_WP, j - S_WQ, DD, DD);
        else if (j < S_WQ + S_WP + S_W1)
            w1[(size_t)layer * S_W1 + (j - S_WQ - S_WP)] = tr_h(fc1_w + (size_t)layer * S_W1, j - S_WQ - S_WP, DD, 1024);
        else
            w2[(size_t)layer * S_W2 + (j - S_WQ - S_WP - S_W1)] = tr_h(fc2_w + (size_t)layer * S_W2, j - S_WQ - S_WP - S_W1, 1024, DD);
    } else {
        int j = i - 2 * LAYER_ELEMS;
        int oc = j / KCONV, kp = j % KCONV;
        int kh = kp >> 8, ic = kp & 255;
        cw[j] = __float2half_rn(conv_w[(size_t)oc * KCONV + ic * 3 + kh]);
    }
}

__global__ void zeropad_kernel(__half* __restrict__ xh2) {
    int i = blockIdx.x * blockDim.x + threadIdx.x;
    if (i >= BB * 2 * DD) return;
    int b = i / (2 * DD);
    int r = (i / DD) & 1;
    int c = i & 255;
    xh2[((size_t)b * LPAD + (r ? (LPAD - 1) : 0)) * DD + c] = __float2half_rn(0.f);
}

// ================= elementwise kernels =================
__global__ void ln_h(const float* __restrict__ x, const float* __restrict__ g,
                     const float* __restrict__ bta, __half* __restrict__ o) {
    int row = blockIdx.x;
    const float* xr = x + (size_t)row * DD;
    float e = xr[threadIdx.x];
    float m = blockReduceSum(e) * (1.0f / DD);
    float d = e - m;
    float var = blockReduceSum(d * d) * (1.0f / DD);
    float r = rsqrtf(var + 1e-5f);
    float v = d * r * g[threadIdx.x] + bta[threadIdx.x];
    o[(size_t)row * DD + threadIdx.x] = __float2half_rn(v);
}

__global__ void ln_plain(const float* __restrict__ x, const float* __restrict__ g,
                         const float* __restrict__ bta, float* __restrict__ out) {
    int row = blockIdx.x;
    const float* xr = x + (size_t)row * OCH;
    float e0 = xr[threadIdx.x], e1 = xr[threadIdx.x + 256];
    float m = blockReduceSum(e0 + e1) * (1.0f / OCH);
    float d0 = e0 - m, d1 = e1 - m;
    float var = blockReduceSum(d0 * d0 + d1 * d1) * (1.0f / OCH);
    float r = rsqrtf(var + 1e-5f);
    float* orow = out + (size_t)row * OCH;
    orow[threadIdx.x]       = d0 * r * g[threadIdx.x] + bta[threadIdx.x];
    orow[threadIdx.x + 256] = d1 * r * g[threadIdx.x + 256] + bta[threadIdx.x + 256];
}

// Neighborhood attention: one THREAD per (token, head). No shuffles.
__global__ void __launch_bounds__(128) nat_attn_kernel(const __half* __restrict__ qkv,
                                                       __half* __restrict__ o) {
    int i = blockIdx.x * blockDim.x + threadIdx.x;
    int h = i & 7, token = i >> 3;
    int l = token & (LL - 1);
    int b = token >> 11;
    const float SCALE = 0.17677669529663687f;
    int start = l - (KWIN / 2);
    if (start < 0) start = 0;
    if (start > LL - KWIN) start = LL - KWIN;

    const __half* qp = qkv + (size_t)token * 768 + h * HDIM;
    __half2 qh[16];
    #pragma unroll
    for (int t = 0; t < 4; t++) {
        uint4 u = ((const uint4*)qp)[t];
        qh[t * 4 + 0] = *(__half2*)&u.x;
        qh[t * 4 + 1] = *(__half2*)&u.y;
        qh[t * 4 + 2] = *(__half2*)&u.z;
        qh[t * 4 + 3] = *(__half2*)&u.w;
    }

    const __half* kbase = qkv + (size_t)(b * LL + start) * 768 + 256 + h * HDIM;
    float s[KWIN];
    #pragma unroll
    for (int j = 0; j < KWIN; j++) {
        const uint4* kv = (const uint4*)(kbase + (size_t)j * 768);
        float acc = 0.f;
        #pragma unroll
        for (int t = 0; t < 4; t++) {
            uint4 u = kv[t];
            uint32_t w[4] = {u.x, u.y, u.z, u.w};
            #pragma unroll
            for (int c = 0; c < 4; c++) {
                float2 a = __half22float2(qh[t * 4 + c]);
                float2 kk = __half22float2(*(__half2*)&w[c]);
                acc += a.x * kk.x + a.y * kk.y;
            }
        }
        s[j] = acc * SCALE;
    }
    float mx = s[0];
    #pragma unroll
    for (int j = 1; j < KWIN; j++) mx = fmaxf(mx, s[j]);
    float sum = 0.f;
    #pragma unroll
    for (int j = 0; j < KWIN; j++) { s[j] = __expf(s[j] - mx); sum += s[j]; }
    float inv = 1.0f / sum;

    const __half* vbase = kbase + 256;
    float2 acc[16];
    #pragma unroll
    for (int t = 0; t < 16; t++) acc[t] = make_float2(0.f, 0.f);
    #pragma unroll
    for (int j = 0; j < KWIN; j++) {
        float w = s[j];
        const uint4* vv = (const uint4*)(vbase + (size_t)j * 768);
        #pragma unroll
        for (int t = 0; t < 4; t++) {
            uint4 u = vv[t];
            uint32_t wd[4] = {u.x, u.y, u.z, u.w};
            #pragma unroll
            for (int c = 0; c < 4; c++) {
                float2 vf = __half22float2(*(__half2*)&wd[c]);
                acc[t * 4 + c].x += w * vf.x;
                acc[t * 4 + c].y += w * vf.y;
            }
        }
    }
    __half* op = o + (size_t)token * DD + h * HDIM;
    #pragma unroll
    for (int t = 0; t < 4; t++) {
        uint4 u;
        uint32_t* wd = (uint32_t*)&u;
        #pragma unroll
        for (int c = 0; c < 4; c++) {
            __half2 hv = __floats2half2_rn(acc[t * 4 + c].x * inv, acc[t * 4 + c].y * inv);
            wd[c] = *(uint32_t*)&hv;
        }
        ((uint4*)op)[t] = u;
    }
}

// ================= single-pass fp16 HMMA GEMM =================
// 128x128 CTA tile, 4 warps (2x2), 64x64 per warp, BK=32, 4-stage cp.async.
#define EPI_NONE        0
#define EPI_GELU_H      2
#define EPI_BIAS_RES    3
#define EPI_BIAS_H      4
#define EPI_BIAS_RES_SH 5

#define ROWB 80
#define MATB (128*ROWB)
#define STAGEB (2*MATB)
#define NSTAGE 4
#define SMEM_SZ (NSTAGE*STAGEB) // 81920

template <int EPI, int ACONV>
__global__ void __launch_bounds__(128) gemm_tc(
    const __half* __restrict__ Am, const __half* __restrict__ Bm,
    const float* __restrict__ bias, const float* __restrict__ res,
    float* __restrict__ C, __half* __restrict__ Oh,
    int M, int N, int K)
{
    extern __shared__ char smem[];
    uint32_t sb = smem_u32(smem);
    int tid = threadIdx.x;
    int warp = tid >> 5, lane = tid & 31;
    int warp_m = warp >> 1, warp_n = warp & 1;
    int m0 = blockIdx.y << 7, n0 = blockIdx.x << 7;

    float acc[4][8][4];
    #pragma unroll
    for (int i = 0; i < 4; i++)
        #pragma unroll
        for (int j = 0; j < 8; j++)
            #pragma unroll
            for (int k = 0; k < 4; k++) acc[i][j][k] = 0.f;

    // load mapping: 128 threads, each loads rows (tid>>1, tid>>1+64), col chunk (tid&1)*16
    int lrow = tid >> 1;
    int lkc  = (tid & 1) * 16;

    int lo0 = m0 & 1023;
    size_t abase = (size_t)(m0 >> 10) * LPAD * DD;

    int a_row = warp_m * 64 + (lane & 7) + ((lane >> 3) & 1) * 8;
    int a_k   = (lane >> 4) * 8;
    int b_n   = warp_n * 64 + (lane & 7) + (lane >> 4) * 8;
    int b_k   = ((lane >> 3) & 1) * 8;

    int nk = K >> 5;
    #define LOAD_STAGE(st, k0) do { \
        uint32_t base_ = sb + (st) * STAGEB; \
        _Pragma("unroll") \
        for (int rr = 0; rr < 2; rr++) { \
            int row_ = lrow + rr * 64; \
            uint32_t sA_ = base_ + row_ * ROWB + lkc * 2; \
            size_t gB_ = (size_t)(n0 + row_) * K + (k0) + lkc; \
            size_t gA_; \
            if (ACONV) { \
                int kh_ = (k0) >> 8; int icb_ = ((k0) & 255) + lkc; \
                gA_ = abase + (size_t)(2 * (lo0 + row_) + kh_) * DD + icb_; \
            } else { \
                gA_ = (size_t)(m0 + row_) * K + (k0) + lkc; \
            } \
            cp16(sA_,             Am + gA_);     cp16(sA_ + 16,        Am + gA_ + 8); \
            cp16(sA_ + MATB,      Bm + gB_);     cp16(sA_ + MATB + 16, Bm + gB_ + 8); \
        } \
        CP_COMMIT(); \
    } while (0)

    #pragma unroll
    for (int s = 0; s < NSTAGE - 1; s++) {
        if (s < nk) LOAD_STAGE(s, s * 32);
        else CP_COMMIT();
    }

    for (int kt = 0; kt < nk; kt++) {
        CP_WAIT(NSTAGE - 2);
        __syncthreads();
        {
            int kn = kt + NSTAGE - 1;
            if (kn < nk) LOAD_STAGE(kn & (NSTAGE - 1), kn * 32);
            else CP_COMMIT();
        }
        uint32_t base = sb + (kt & (NSTAGE - 1)) * STAGEB;
        #pragma unroll
        for (int ks = 0; ks < 2; ks++) {
            int k = ks * 16;
            uint32_t ah[4][4];
            #pragma unroll
            for (int mt = 0; mt < 4; mt++) {
                uint32_t eo = base + (uint32_t)(a_row + mt * 16) * ROWB + (uint32_t)(k + a_k) * 2;
                ldsm4(ah[mt], eo);
            }
            #pragma unroll
            for (int p = 0; p < 4; p++) {
                uint32_t eo = base + MATB + (uint32_t)(b_n + p * 16) * ROWB + (uint32_t)(k + b_k) * 2;
                uint32_t b4[4];
                ldsm4(b4, eo);
                #pragma unroll
                for (int mt = 0; mt < 4; mt++) {
                    mma16816(acc[mt][2 * p],     ah[mt], b4[0], b4[1]);
                    mma16816(acc[mt][2 * p + 1], ah[mt], b4[2], b4[3]);
                }
            }
        }
    }

    // epilogue
    int group = lane >> 2, tg = lane & 3;
    #pragma unroll
    for (int mt = 0; mt < 4; mt++) {
        #pragma unroll
        for (int half = 0; half < 2; half++) {
            int m = m0 + warp_m * 64 + mt * 16 + group + half * 8;
            #pragma unroll
            for (int nt = 0; nt < 8; nt++) {
                int n = n0 + warp_n * 64 + nt * 8 + tg * 2;
                float v0 = acc[mt][nt][half * 2 + 0];
                float v1 = acc[mt][nt][half * 2 + 1];
                if (EPI != EPI_NONE) { v0 += bias[n]; v1 += bias[n + 1]; }
                if (EPI == EPI_GELU_H) {
                    v0 = 0.5f * v0 * (1.0f + erff(v0 * 0.70710678118654752f));
                    v1 = 0.5f * v1 * (1.0f + erff(v1 * 0.70710678118654752f));
                    *(__half2*)&Oh[(size_t)m * N + n] =
                        __halves2half2(__float2half_rn(v0), __float2half_rn(v1));
                } else if (EPI == EPI_BIAS_H) {
                    *(__half2*)&Oh[(size_t)m * N + n] =
                        __halves2half2(__float2half_rn(v0), __float2half_rn(v1));
                } else {
                    if (EPI == EPI_BIAS_RES || EPI == EPI_BIAS_RES_SH) {
                        float2 rr = *(const float2*)&res[(size_t)m * N + n];
                        v0 += rr.x; v1 += rr.y;
                    }
                    *(float2*)&C[(size_t)m * N + n] = make_float2(v0, v1);
                    if (EPI == EPI_BIAS_RES_SH) {
                        int b_ = m >> 11, t_ = m & (LL - 1);
                        size_t sh = ((size_t)b_ * LPAD + t_ + 1) * DD + n;
                        *(__half2*)&Oh[sh] =
                            __halves2half2(__float2half_rn(v0), __float2half_rn(v1));
                    }
                }
            }
        }
    }
}

// ================= launch =================
extern "C" void kernel_launch(void* const* d_in, const int* in_sizes, int n_in,
                              void* d_out, int out_size)
{
    const float* x_in   = (const float*)d_in[0];
    const float* ln1_g  = (const float*)d_in[1];
    const float* ln1_b  = (const float*)d_in[2];
    const float* qkv_w  = (const float*)d_in[3];
    const float* qkv_b  = (const float*)d_in[4];
    const float* proj_w = (const float*)d_in[5];
    const float* proj_b = (const float*)d_in[6];
    const float* ln2_g  = (const float*)d_in[7];
    const float* ln2_b  = (const float*)d_in[8];
    const float* fc1_w  = (const float*)d_in[9];
    const float* fc1_b  = (const float*)d_in[10];
    const float* fc2_w  = (const float*)d_in[11];
    const float* fc2_b  = (const float*)d_in[12];
    const float* conv_w = (const float*)d_in[13];
    const float* dn_g   = (const float*)d_in[14];
    const float* dn_b   = (const float*)d_in[15];

    float* y_out = (float*)d_out;
    float* xbuf  = y_out + Y_ELEMS;

    void* p;
    #define GET(sym, var) cudaGetSymbolAddress(&p, sym); auto* var = (decltype(&sym[0]))p;
    GET(g_t0, t0) GET(g_qkvh, qkvh) GET(g_at, at) GET(g_hi, hi)
    GET(g_xh2, xh2) GET(g_conv, conv)
    GET(g_wq, wq) GET(g_wp, wp) GET(g_w1, w1) GET(g_w2, w2) GET(g_cw, cw)
    #undef GET

    cudaFuncSetAttribute((const void*)gemm_tc<EPI_BIAS_H, 0>,      cudaFuncAttributeMaxDynamicSharedMemorySize, SMEM_SZ);
    cudaFuncSetAttribute((const void*)gemm_tc<EPI_BIAS_RES, 0>,    cudaFuncAttributeMaxDynamicSharedMemorySize, SMEM_SZ);
    cudaFuncSetAttribute((const void*)gemm_tc<EPI_GELU_H, 0>,      cudaFuncAttributeMaxDynamicSharedMemorySize, SMEM_SZ);
    cudaFuncSetAttribute((const void*)gemm_tc<EPI_BIAS_RES_SH, 0>, cudaFuncAttributeMaxDynamicSharedMemorySize, SMEM_SZ);
    cudaFuncSetAttribute((const void*)gemm_tc<EPI_NONE, 1>,        cudaFuncAttributeMaxDynamicSharedMemorySize, SMEM_SZ);

    prep_kernel<<<PREP_TOTAL / 256, 256>>>(qkv_w, proj_w, fc1_w, fc2_w, conv_w, wq, wp, w1, w2, cw);
    zeropad_kernel<<<(BB * 2 * DD + 255) / 256, 256>>>(xh2);

    for (int i = 0; i < NDEPTH; i++) {
        const float* xin = (i == 0) ? x_in : xbuf;
        ln_h<<<NTOK, 256>>>(xin, ln1_g + i * DD, ln1_b + i * DD, t0);
        {   // qkv -> fp16
            dim3 g(768 / 128, NTOK / 128);
            gemm_tc<EPI_BIAS_H, 0><<<g, 128, SMEM_SZ>>>(t0, wq + (size_t)i * 768 * DD,
                qkv_b + i * 768, nullptr, nullptr, qkvh, NTOK, 768, DD);
        }
        nat_attn_kernel<<<NTOK * HH / 128, 128>>>(qkvh, at);
        {   // proj + residual
            dim3 g(DD / 128, NTOK / 128);
            gemm_tc<EPI_BIAS_RES, 0><<<g, 128, SMEM_SZ>>>(at, wp + (size_t)i * DD * DD,
                proj_b + i * DD, xin, xbuf, nullptr, NTOK, DD, DD);
        }
        ln_h<<<NTOK, 256>>>(xbuf, ln2_g + i * DD, ln2_b + i * DD, t0);
        {   // fc1 + gelu -> fp16
            dim3 g(1024 / 128, NTOK / 128);
            gemm_tc<EPI_GELU_H, 0><<<g, 128, SMEM_SZ>>>(t0, w1 + (size_t)i * 1024 * DD,
                fc1_b + i * 1024, nullptr, nullptr, hi, NTOK, 1024, DD);
        }
        if (i < NDEPTH - 1) {
            dim3 g(DD / 128, NTOK / 128);
            gemm_tc<EPI_BIAS_RES, 0><<<g, 128, SMEM_SZ>>>(hi, w2 + (size_t)i * DD * 1024,
                fc2_b + i * DD, xbuf, xbuf, nullptr, NTOK, DD, 1024);
        } else {
            dim3 g(DD / 128, NTOK / 128);
            gemm_tc<EPI_BIAS_RES_SH, 0><<<g, 128, SMEM_SZ>>>(hi, w2 + (size_t)i * DD * 1024,
                fc2_b + i * DD, xbuf, xbuf, xh2, NTOK, DD, 1024);
        }
    }

    {   // conv GEMM reads shadow directly
        dim3 g(OCH / 128, (BB * LOUT) / 128);
        gemm_tc<EPI_NONE, 1><<<g, 128, SMEM_SZ>>>(xh2, cw,
            nullptr, nullptr, conv, nullptr, BB * LOUT, OCH, KCONV);
    }
    ln_plain<<<BB * LOUT, 256>>>(conv, dn_g, dn_b, y_out);
}

// round 15
// speedup vs baseline: 1.2830x; 1.2830x over previous
#include <cuda_runtime.h>
#include <cuda_fp16.h>
#include <cstdint>
#include <math.h>

#define BB 16
#define LL 2048
#define DD 256
#define HH 8
#define HDIM 32
#define KWIN 7
#define NDEPTH 2
#define LOUT 1024
#define OCH 512
#define KCONV 768
#define NTOK (BB*LL)
#define Y_ELEMS (BB*LOUT*OCH)
#define LPAD (LL+2)

// ================= scratch =================
__device__ __half g_t0[(size_t)NTOK*DD];
__device__ __half g_qkvh[(size_t)NTOK*3*DD];
__device__ __half g_at[(size_t)NTOK*DD];
__device__ __half g_hi[(size_t)NTOK*4*DD];
__device__ __half g_xh2[(size_t)BB*LPAD*DD];
__device__ float  g_conv[(size_t)BB*LOUT*OCH];
__device__ __half g_wq[(size_t)NDEPTH*768*DD];
__device__ __half g_wp[(size_t)NDEPTH*DD*DD];
__device__ __half g_w1[(size_t)NDEPTH*1024*DD];
__device__ __half g_w2[(size_t)NDEPTH*DD*1024];
__device__ __half g_cw[(size_t)OCH*KCONV];

// ================= helpers =================
__device__ __forceinline__ uint32_t smem_u32(const void* p) {
    uint32_t a;
    asm("{ .reg .u64 t; cvta.to.shared.u64 t, %1; cvt.u32.u64 %0, t; }" : "=r"(a) : "l"(p));
    return a;
}
__device__ __forceinline__ void cp16(uint32_t s, const void* g) {
    asm volatile("cp.async.cg.shared.global [%0], [%1], 16;" :: "r"(s), "l"(g));
}
#define CP_COMMIT() asm volatile("cp.async.commit_group;" ::: "memory")
#define CP_WAIT(n)  asm volatile("cp.async.wait_group %0;" :: "n"(n) : "memory")

__device__ __forceinline__ void ldsm4(uint32_t* r, uint32_t addr) {
    asm volatile("ldmatrix.sync.aligned.m8n8.x4.shared.b16 {%0,%1,%2,%3}, [%4];"
        : "=r"(r[0]), "=r"(r[1]), "=r"(r[2]), "=r"(r[3]) : "r"(addr));
}
__device__ __forceinline__ void mma16816(float* c, const uint32_t* a, uint32_t b0, uint32_t b1) {
    asm volatile(
        "mma.sync.aligned.m16n8k16.row.col.f32.f16.f16.f32 "
        "{%0,%1,%2,%3}, {%4,%5,%6,%7}, {%8,%9}, {%0,%1,%2,%3};"
        : "+f"(c[0]), "+f"(c[1]), "+f"(c[2]), "+f"(c[3])
        : "r"(a[0]), "r"(a[1]), "r"(a[2]), "r"(a[3]), "r"(b0), "r"(b1));
}

__device__ __forceinline__ float warpSum(float v) {
    #pragma unroll
    for (int o = 16; o; o >>= 1) v += __shfl_xor_sync(0xffffffffu, v, o);
    return v;
}

// ================= weight prep (+ shadow pad zeroing) =================
#define S_WQ  (768*DD)
#define S_WP  (DD*DD)
#define S_W1  (1024*DD)
#define S_W2  (DD*1024)
#define LAYER_ELEMS (S_WQ + S_WP + S_W1 + S_W2)
#define CONV_ELEMS  (OCH*KCONV)
#define PAD_ELEMS   (BB*2*DD)
#define PREP_TOTAL  (2*LAYER_ELEMS + CONV_ELEMS + PAD_ELEMS)

__device__ __forceinline__ __half tr_h(const float* src, int j, int K, int N) {
    int n = j / K, kk = j % K;
    return __float2half_rn(src[(size_t)kk * N + n]);
}

__global__ void prep_kernel(const float* __restrict__ qkv_w, const float* __restrict__ proj_w,
                            const float* __restrict__ fc1_w, const float* __restrict__ fc2_w,
                            const float* __restrict__ conv_w,
                            __half* __restrict__ wq, __half* __restrict__ wp,
                            __half* __restrict__ w1, __half* __restrict__ w2,
                            __half* __restrict__ cw, __half* __restrict__ xh2) {
    int i = blockIdx.x * blockDim.x + threadIdx.x;
    if (i >= PREP_TOTAL) return;
    if (i < 2 * LAYER_ELEMS) {
        int layer = i / LAYER_ELEMS;
        int j = i - layer * LAYER_ELEMS;
        if (j < S_WQ)
            wq[(size_t)layer * S_WQ + j] = tr_h(qkv_w + (size_t)layer * S_WQ, j, DD, 768);
        else if (j < S_WQ + S_WP)
            wp[(size_t)layer * S_WP + (j - S_WQ)] = tr_h(proj_w + (size_t)layer * S_WP, j - S_WQ, DD, DD);
        else if (j < S_WQ + S_WP + S_W1)
            w1[(size_t)layer * S_W1 + (j - S_WQ - S_WP)] = tr_h(fc1_w + (size_t)layer * S_W1, j - S_WQ - S_WP, DD, 1024);
        else
            w2[(size_t)layer * S_W2 + (j - S_WQ - S_WP - S_W1)] = tr_h(fc2_w + (size_t)layer * S_W2, j - S_WQ - S_WP - S_W1, 1024, DD);
    } else if (i < 2 * LAYER_ELEMS + CONV_ELEMS) {
        int j = i - 2 * LAYER_ELEMS;
        int oc = j / KCONV, kp = j % KCONV;
        int kh = kp >> 8, ic = kp & 255;
        cw[j] = __float2half_rn(conv_w[(size_t)oc * KCONV + ic * 3 + kh]);
    } else {
        int j = i - 2 * LAYER_ELEMS - CONV_ELEMS;
        int b = j / (2 * DD);
        int r = (j / DD) & 1;
        int c = j & 255;
        xh2[((size_t)b * LPAD + (r ? (LPAD - 1) : 0)) * DD + c] = __float2half_rn(0.f);
    }
}

// ================= LayerNorms: warp-per-row =================
__global__ void __launch_bounds__(256) ln_h(const float* __restrict__ x, const float* __restrict__ g,
                                            const float* __restrict__ bta, __half* __restrict__ o) {
    int warp = threadIdx.x >> 5, lane = threadIdx.x & 31;
    int row = blockIdx.x * 8 + warp;
    const float4* xr = (const float4*)(x + (size_t)row * DD);
    float4 a = xr[lane], b = xr[lane + 32];
    float m = warpSum(a.x + a.y + a.z + a.w + b.x + b.y + b.z + b.w) * (1.0f / DD);
    float dx0 = a.x - m, dx1 = a.y - m, dx2 = a.z - m, dx3 = a.w - m;
    float dy0 = b.x - m, dy1 = b.y - m, dy2 = b.z - m, dy3 = b.w - m;
    float var = warpSum(dx0*dx0 + dx1*dx1 + dx2*dx2 + dx3*dx3 +
                        dy0*dy0 + dy1*dy1 + dy2*dy2 + dy3*dy3) * (1.0f / DD);
    float r = rsqrtf(var + 1e-5f);
    int c0 = lane * 4, c1 = 128 + lane * 4;
    float4 ga = *(const float4*)&g[c0],  gb = *(const float4*)&g[c1];
    float4 ba = *(const float4*)&bta[c0], bb = *(const float4*)&bta[c1];
    __half2 h0 = __floats2half2_rn(dx0 * r * ga.x + ba.x, dx1 * r * ga.y + ba.y);
    __half2 h1 = __floats2half2_rn(dx2 * r * ga.z + ba.z, dx3 * r * ga.w + ba.w);
    __half2 h2 = __floats2half2_rn(dy0 * r * gb.x + bb.x, dy1 * r * gb.y + bb.y);
    __half2 h3 = __floats2half2_rn(dy2 * r * gb.z + bb.z, dy3 * r * gb.w + bb.w);
    __half* orow = o + (size_t)row * DD;
    *(uint2*)&orow[c0] = make_uint2(*(uint32_t*)&h0, *(uint32_t*)&h1);
    *(uint2*)&orow[c1] = make_uint2(*(uint32_t*)&h2, *(uint32_t*)&h3);
}

__global__ void __launch_bounds__(256) ln_plain(const float* __restrict__ x, const float* __restrict__ g,
                                                const float* __restrict__ bta, float* __restrict__ out) {
    int warp = threadIdx.x >> 5, lane = threadIdx.x & 31;
    int row = blockIdx.x * 8 + warp;
    const float4* xr = (const float4*)(x + (size_t)row * OCH);
    float4 e[4];
    float sum = 0.f;
    #pragma unroll
    for (int t = 0; t < 4; t++) {
        e[t] = xr[lane + 32 * t];
        sum += e[t].x + e[t].y + e[t].z + e[t].w;
    }
    float m = warpSum(sum) * (1.0f / OCH);
    float sq = 0.f;
    #pragma unroll
    for (int t = 0; t < 4; t++) {
        e[t].x -= m; e[t].y -= m; e[t].z -= m; e[t].w -= m;
        sq += e[t].x*e[t].x + e[t].y*e[t].y + e[t].z*e[t].z + e[t].w*e[t].w;
    }
    float r = rsqrtf(warpSum(sq) * (1.0f / OCH) + 1e-5f);
    float* orow = out + (size_t)row * OCH;
    #pragma unroll
    for (int t = 0; t < 4; t++) {
        int c = lane * 4 + 128 * t;
        float4 gv = *(const float4*)&g[c];
        float4 bv = *(const float4*)&bta[c];
        *(float4*)&orow[c] = make_float4(e[t].x * r * gv.x + bv.x, e[t].y * r * gv.y + bv.y,
                                         e[t].z * r * gv.z + bv.z, e[t].w * r * gv.w + bv.w);
    }
}

// ================= neighborhood attention, smem-tiled =================
#define AT_ROWS 136
#define AT_RP 40               // padded row: 32 + 8 halves = 80 bytes
__global__ void __launch_bounds__(128) nat_attn_kernel(const __half* __restrict__ qkv,
                                                       __half* __restrict__ o) {
    __shared__ __half ks[AT_ROWS * AT_RP];
    __shared__ __half vs[AT_ROWS * AT_RP];
    int blk = blockIdx.x;
    int h = blk & 7, chunk = (blk >> 3) & 15, b = blk >> 7;
    int t0 = chunk << 7;
    int lo = t0 - 3;
    for (int r = threadIdx.x; r < 134; r += 128) {
        int t = lo + r;
        if (t >= 0 && t < LL) {
            const uint4* src = (const uint4*)(qkv + (size_t)(b * LL + t) * 768 + 256 + h * HDIM);
            uint4* dk = (uint4*)&ks[r * AT_RP];
            uint4* dv = (uint4*)&vs[r * AT_RP];
            #pragma unroll
            for (int c = 0; c < 4; c++) { dk[c] = src[c]; dv[c] = src[c + 32]; } // v = k + 256 halves = +32 uint4
        }
    }
    __syncthreads();

    int l = t0 + threadIdx.x;
    int token = b * LL + l;
    const float SCALE = 0.17677669529663687f;
    int start = l - 3;
    if (start < 0) start = 0;
    if (start > LL - KWIN) start = LL - KWIN;
    int rbase = start - lo;

    __half2 qh[16];
    const uint4* qp = (const uint4*)(qkv + (size_t)token * 768 + h * HDIM);
    #pragma unroll
    for (int t = 0; t < 4; t++) {
        uint4 u = qp[t];
        qh[t * 4 + 0] = *(__half2*)&u.x;
        qh[t * 4 + 1] = *(__half2*)&u.y;
        qh[t * 4 + 2] = *(__half2*)&u.z;
        qh[t * 4 + 3] = *(__half2*)&u.w;
    }

    float s[KWIN];
    #pragma unroll
    for (int j = 0; j < KWIN; j++) {
        const uint4* kr = (const uint4*)&ks[(rbase + j) * AT_RP];
        float acc = 0.f;
        #pragma unroll
        for (int t = 0; t < 4; t++) {
            uint4 u = kr[t];
            uint32_t w[4] = {u.x, u.y, u.z, u.w};
            #pragma unroll
            for (int c = 0; c < 4; c++) {
                float2 a = __half22float2(qh[t * 4 + c]);
                float2 kk = __half22float2(*(__half2*)&w[c]);
                acc += a.x * kk.x + a.y * kk.y;
            }
        }
        s[j] = acc * SCALE;
    }
    float mx = s[0];
    #pragma unroll
    for (int j = 1; j < KWIN; j++) mx = fmaxf(mx, s[j]);
    float sum = 0.f;
    #pragma unroll
    for (int j = 0; j < KWIN; j++) { s[j] = __expf(s[j] - mx); sum += s[j]; }
    float inv = 1.0f / sum;

    float2 acc[16];
    #pragma unroll
    for (int t = 0; t < 16; t++) acc[t] = make_float2(0.f, 0.f);
    #pragma unroll
    for (int j = 0; j < KWIN; j++) {
        float w = s[j];
        const uint4* vr = (const uint4*)&vs[(rbase + j) * AT_RP];
        #pragma unroll
        for (int t = 0; t < 4; t++) {
            uint4 u = vr[t];
            uint32_t wd[4] = {u.x, u.y, u.z, u.w};
            #pragma unroll
            for (int c = 0; c < 4; c++) {
                float2 vf = __half22float2(*(__half2*)&wd[c]);
                acc[t * 4 + c].x += w * vf.x;
                acc[t * 4 + c].y += w * vf.y;
            }
        }
    }
    __half* op = o + (size_t)token * DD + h * HDIM;
    #pragma unroll
    for (int t = 0; t < 4; t++) {
        uint4 u;
        uint32_t* wd = (uint32_t*)&u;
        #pragma unroll
        for (int c = 0; c < 4; c++) {
            __half2 hv = __floats2half2_rn(acc[t * 4 + c].x * inv, acc[t * 4 + c].y * inv);
            wd[c] = *(uint32_t*)&hv;
        }
        ((uint4*)op)[t] = u;
    }
}

// ================= single-pass fp16 HMMA GEMM (R7 config) =================
#define EPI_NONE        0
#define EPI_GELU_H      2
#define EPI_BIAS_RES    3
#define EPI_BIAS_H      4
#define EPI_BIAS_RES_SH 5

#define ROWB 80
#define MATB (128*ROWB)
#define STAGEB (2*MATB)
#define NSTAGE 4
#define SMEM_SZ (NSTAGE*STAGEB) // 81920

template <int EPI, int ACONV>
__global__ void __launch_bounds__(256) gemm_tc(
    const __half* __restrict__ Am, const __half* __restrict__ Bm,
    const float* __restrict__ bias, const float* __restrict__ res,
    float* __restrict__ C, __half* __restrict__ Oh,
    int M, int N, int K)
{
    extern __shared__ char smem[];
    uint32_t sb = smem_u32(smem);
    int tid = threadIdx.x;
    int warp = tid >> 5, lane = tid & 31;
    int warp_m = warp >> 1, warp_n = warp & 1;
    int m0 = blockIdx.y << 7, n0 = blockIdx.x << 7;

    float acc[2][8][4];
    #pragma unroll
    for (int i = 0; i < 2; i++)
        #pragma unroll
        for (int j = 0; j < 8; j++)
            #pragma unroll
            for (int k = 0; k < 4; k++) acc[i][j][k] = 0.f;

    int r0c = tid >> 2, kc0 = (tid & 3) * 8;
    int r1c = r0c + 64;

    int lo0 = m0 & 1023;
    size_t abase = (size_t)(m0 >> 10) * LPAD * DD;

    int a_row = warp_m * 32 + (lane & 7) + ((lane >> 3) & 1) * 8;
    int a_k   = (lane >> 4) * 8;
    int b_n   = warp_n * 64 + (lane & 7) + (lane >> 4) * 8;
    int b_k   = ((lane >> 3) & 1) * 8;

    int nk = K >> 5;
    #define LOAD_STAGE(st, k0) do { \
        uint32_t base_ = sb + (st) * STAGEB; \
        uint32_t s0_ = base_ + r0c * ROWB + kc0 * 2; \
        uint32_t s1_ = base_ + r1c * ROWB + kc0 * 2; \
        size_t gB0_ = (size_t)(n0 + r0c) * K + (k0) + kc0; \
        size_t gB1_ = (size_t)(n0 + r1c) * K + (k0) + kc0; \
        size_t gA0_, gA1_; \
        if (ACONV) { \
            int kh_ = (k0) >> 8; int icb_ = ((k0) & 255) + kc0; \
            gA0_ = abase + (size_t)(2 * (lo0 + r0c) + kh_) * DD + icb_; \
            gA1_ = abase + (size_t)(2 * (lo0 + r1c) + kh_) * DD + icb_; \
        } else { \
            gA0_ = (size_t)(m0 + r0c) * K + (k0) + kc0; \
            gA1_ = (size_t)(m0 + r1c) * K + (k0) + kc0; \
        } \
        cp16(s0_,        Am + gA0_); cp16(s1_,        Am + gA1_); \
        cp16(s0_ + MATB, Bm + gB0_); cp16(s1_ + MATB, Bm + gB1_); \
        CP_COMMIT(); \
    } while (0)

    #pragma unroll
    for (int s = 0; s < NSTAGE - 1; s++) {
        if (s < nk) LOAD_STAGE(s, s * 32);
        else CP_COMMIT();
    }

    for (int kt = 0; kt < nk; kt++) {
        CP_WAIT(NSTAGE - 2);
        __syncthreads();
        {
            int kn = kt + NSTAGE - 1;
            if (kn < nk) LOAD_STAGE(kn & (NSTAGE - 1), kn * 32);
            else CP_COMMIT();
        }
        uint32_t base = sb + (kt & (NSTAGE - 1)) * STAGEB;
        #pragma unroll
        for (int ks = 0; ks < 2; ks++) {
            int k = ks * 16;
            uint32_t ah[2][4];
            #pragma unroll
            for (int mt = 0; mt < 2; mt++) {
                uint32_t eo = base + (uint32_t)(a_row + mt * 16) * ROWB + (uint32_t)(k + a_k) * 2;
                ldsm4(ah[mt], eo);
            }
            #pragma unroll
            for (int p = 0; p < 4; p++) {
                uint32_t eo = base + MATB + (uint32_t)(b_n + p * 16) * ROWB + (uint32_t)(k + b_k) * 2;
                uint32_t b4[4];
                ldsm4(b4, eo);
                #pragma unroll
                for (int mt = 0; mt < 2; mt++) {
                    mma16816(acc[mt][2 * p],     ah[mt], b4[0], b4[1]);
                    mma16816(acc[mt][2 * p + 1], ah[mt], b4[2], b4[3]);
                }
            }
        }
    }

    // epilogue
    int group = lane >> 2, tg = lane & 3;
    #pragma unroll
    for (int mt = 0; mt < 2; mt++) {
        #pragma unroll
        for (int half = 0; half < 2; half++) {
            int m = m0 + warp_m * 32 + mt * 16 + group + half * 8;
            #pragma unroll
            for (int nt = 0; nt < 8; nt++) {
                int n = n0 + warp_n * 64 + nt * 8 + tg * 2;
                float v0 = acc[mt][nt][half * 2 + 0];
                float v1 = acc[mt][nt][half * 2 + 1];
                if (EPI != EPI_NONE) { v0 += bias[n]; v1 += bias[n + 1]; }
                if (EPI == EPI_GELU_H) {
                    v0 = 0.5f * v0 * (1.0f + erff(v0 * 0.70710678118654752f));
                    v1 = 0.5f * v1 * (1.0f + erff(v1 * 0.70710678118654752f));
                    *(__half2*)&Oh[(size_t)m * N + n] =
                        __halves2half2(__float2half_rn(v0), __float2half_rn(v1));
                } else if (EPI == EPI_BIAS_H) {
                    *(__half2*)&Oh[(size_t)m * N + n] =
                        __halves2half2(__float2half_rn(v0), __float2half_rn(v1));
                } else {
                    if (EPI == EPI_BIAS_RES || EPI == EPI_BIAS_RES_SH) {
                        float2 rr = *(const float2*)&res[(size_t)m * N + n];
                        v0 += rr.x; v1 += rr.y;
                    }
                    *(float2*)&C[(size_t)m * N + n] = make_float2(v0, v1);
                    if (EPI == EPI_BIAS_RES_SH) {
                        int b_ = m >> 11, t_ = m & (LL - 1);
                        size_t sh = ((size_t)b_ * LPAD + t_ + 1) * DD + n;
                        *(__half2*)&Oh[sh] =
                            __halves2half2(__float2half_rn(v0), __float2half_rn(v1));
                    }
                }
            }
        }
    }
}

// ================= launch =================
extern "C" void kernel_launch(void* const* d_in, const int* in_sizes, int n_in,
                              void* d_out, int out_size)
{
    const float* x_in   = (const float*)d_in[0];
    const float* ln1_g  = (const float*)d_in[1];
    const float* ln1_b  = (const float*)d_in[2];
    const float* qkv_w  = (const float*)d_in[3];
    const float* qkv_b  = (const float*)d_in[4];
    const float* proj_w = (const float*)d_in[5];
    const float* proj_b = (const float*)d_in[6];
    const float* ln2_g  = (const float*)d_in[7];
    const float* ln2_b  = (const float*)d_in[8];
    const float* fc1_w  = (const float*)d_in[9];
    const float* fc1_b  = (const float*)d_in[10];
    const float* fc2_w  = (const float*)d_in[11];
    const float* fc2_b  = (const float*)d_in[12];
    const float* conv_w = (const float*)d_in[13];
    const float* dn_g   = (const float*)d_in[14];
    const float* dn_b   = (const float*)d_in[15];

    float* y_out = (float*)d_out;
    float* xbuf  = y_out + Y_ELEMS;

    void* p;
    #define GET(sym, var) cudaGetSymbolAddress(&p, sym); auto* var = (decltype(&sym[0]))p;
    GET(g_t0, t0) GET(g_qkvh, qkvh) GET(g_at, at) GET(g_hi, hi)
    GET(g_xh2, xh2) GET(g_conv, conv)
    GET(g_wq, wq) GET(g_wp, wp) GET(g_w1, w1) GET(g_w2, w2) GET(g_cw, cw)
    #undef GET

    cudaFuncSetAttribute((const void*)gemm_tc<EPI_BIAS_H, 0>,      cudaFuncAttributeMaxDynamicSharedMemorySize, SMEM_SZ);
    cudaFuncSetAttribute((const void*)gemm_tc<EPI_BIAS_RES, 0>,    cudaFuncAttributeMaxDynamicSharedMemorySize, SMEM_SZ);
    cudaFuncSetAttribute((const void*)gemm_tc<EPI_GELU_H, 0>,      cudaFuncAttributeMaxDynamicSharedMemorySize, SMEM_SZ);
    cudaFuncSetAttribute((const void*)gemm_tc<EPI_BIAS_RES_SH, 0>, cudaFuncAttributeMaxDynamicSharedMemorySize, SMEM_SZ);
    cudaFuncSetAttribute((const void*)gemm_tc<EPI_NONE, 1>,        cudaFuncAttributeMaxDynamicSharedMemorySize, SMEM_SZ);

    prep_kernel<<<(PREP_TOTAL + 255) / 256, 256>>>(qkv_w, proj_w, fc1_w, fc2_w, conv_w,
                                                   wq, wp, w1, w2, cw, xh2);

    for (int i = 0; i < NDEPTH; i++) {
        const float* xin = (i == 0) ? x_in : xbuf;
        ln_h<<<NTOK / 8, 256>>>(xin, ln1_g + i * DD, ln1_b + i * DD, t0);
        {   // qkv -> fp16
            dim3 g(768 / 128, NTOK / 128);
            gemm_tc<EPI_BIAS_H, 0><<<g, 256, SMEM_SZ>>>(t0, wq + (size_t)i * 768 * DD,
                qkv_b + i * 768, nullptr, nullptr, qkvh, NTOK, 768, DD);
        }
        nat_attn_kernel<<<BB * 16 * HH, 128>>>(qkvh, at);
        {   // proj + residual
            dim3 g(DD / 128, NTOK / 128);
            gemm_tc<EPI_BIAS_RES, 0><<<g, 256, SMEM_SZ>>>(at, wp + (size_t)i * DD * DD,
                proj_b + i * DD, xin, xbuf, nullptr, NTOK, DD, DD);
        }
        ln_h<<<NTOK / 8, 256>>>(xbuf, ln2_g + i * DD, ln2_b + i * DD, t0);
        {   // fc1 + gelu -> fp16
            dim3 g(1024 / 128, NTOK / 128);
            gemm_tc<EPI_GELU_H, 0><<<g, 256, SMEM_SZ>>>(t0, w1 + (size_t)i * 1024 * DD,
                fc1_b + i * 1024, nullptr, nullptr, hi, NTOK, 1024, DD);
        }
        if (i < NDEPTH - 1) {
            dim3 g(DD / 128, NTOK / 128);
            gemm_tc<EPI_BIAS_RES, 0><<<g, 256, SMEM_SZ>>>(hi, w2 + (size_t)i * DD * 1024,
                fc2_b + i * DD, xbuf, xbuf, nullptr, NTOK, DD, 1024);
        } else {
            dim3 g(DD / 128, NTOK / 128);
            gemm_tc<EPI_BIAS_RES_SH, 0><<<g, 256, SMEM_SZ>>>(hi, w2 + (size_t)i * DD * 1024,
                fc2_b + i * DD, xbuf, xbuf, xh2, NTOK, DD, 1024);
        }
    }

    {   // conv GEMM reads shadow directly
        dim3 g(OCH / 128, (BB * LOUT) / 128);
        gemm_tc<EPI_NONE, 1><<<g, 256, SMEM_SZ>>>(xh2, cw,
            nullptr, nullptr, conv, nullptr, BB * LOUT, OCH, KCONV);
    }
    ln_plain<<<(BB * LOUT) / 8, 256>>>(conv, dn_g, dn_b, y_out);
}